// round 3
// baseline (speedup 1.0000x reference)
#include <cuda_runtime.h>
#include <math.h>
#include <float.h>

#define B_   16
#define C_   64
#define N_   2048
#define K_   20
#define KS_  20
#define OUT_ 128
#define G_   (B_*N_)          // 32768 columns
#define TN   8                // columns per block
#define NBLK (G_/TN)          // 4096
#define THR  256
#define FSTR 1284             // padded per-column stride (floats): col offset % 128B keeps banks spread
#define EPS_ 1e-5f

// ---- device scratch (no allocations allowed) ----
__device__ float g_xT[G_*C_];             // 8 MB: x transposed to (B*N, C)
__device__ float g_part[NBLK*OUT_*2];     // 4 MB: per-block (sum, sumsq) per channel
__device__ float g_scale[OUT_];
__device__ float g_shift[OUT_];

// ============================================================
// Kernel 0: transpose x (B,C,N) -> xT (B*N, C), smem-tiled
// ============================================================
__global__ void transpose_k(const float* __restrict__ x) {
    __shared__ float t[32][33];
    int b  = blockIdx.z;
    int n0 = blockIdx.x * 32, c0 = blockIdx.y * 32;
    int tx = threadIdx.x, ty = threadIdx.y;
    #pragma unroll
    for (int i = ty; i < 32; i += 8)
        t[i][tx] = x[((size_t)b*C_ + c0 + i)*N_ + n0 + tx];
    __syncthreads();
    #pragma unroll
    for (int i = ty; i < 32; i += 8)
        g_xT[((size_t)b*N_ + n0 + i)*C_ + c0 + tx] = t[tx][i];
}

// ============================================================
// Kernel 1: fused gather + feats + out2 + out4 (pre-BN) + partial stats
// ============================================================
__global__ __launch_bounds__(THR, 2)
void main_k(const int*   __restrict__ sidx,
            const float* __restrict__ adjw,
            const float* __restrict__ W2,
            const float* __restrict__ b2,
            const float* __restrict__ W4,
            float*       __restrict__ out)
{
    extern __shared__ float sm[];
    float* S  = sm;                      // TN*FSTR: S[col][i*64+f]
    float* F  = S + TN*FSTR;             // TN*FSTR: feats[col][f*20+k]
    float* AW = F + TN*FSTR;             // 64*68 floats: first A[col*400+i*20+k] (3200), later W4a rows (stride 68)
    float* XR = AW + 64*68;              // TN*64: x row per column

    const int tid = threadIdx.x;
    const int g0  = blockIdx.x * TN;

    // ---- gather spiral rows into S (float4, coalesced over xT rows) ----
    for (int j = tid; j < TN*K_*16; j += THR) {
        int col = j / (K_*16);
        int r   = j % (K_*16);
        int i   = r >> 4, q = r & 15;
        int p   = sidx[(g0 + col)*K_ + i];
        float4 v = ((const float4*)g_xT)[(size_t)p*16 + q];
        float* d = &S[col*FSTR + i*64 + q*4];
        d[0]=v.x; d[1]=v.y; d[2]=v.z; d[3]=v.w;
    }
    // ---- adjweight tile ----
    for (int j = tid; j < TN*100; j += THR) {
        int col = j/100, q = j%100;
        float4 v = ((const float4*)adjw)[(size_t)(g0+col)*100 + q];
        float* d = &AW[col*400 + q*4];
        d[0]=v.x; d[1]=v.y; d[2]=v.z; d[3]=v.w;
    }
    // ---- x rows ----
    for (int j = tid; j < TN*16; j += THR) {
        float4 v = ((const float4*)g_xT)[(size_t)(g0 + j/16)*16 + (j & 15)];
        float* d = &XR[(j/16)*64 + (j & 15)*4];
        d[0]=v.x; d[1]=v.y; d[2]=v.z; d[3]=v.w;
    }
    __syncthreads();

    // ---- feats[col][f*20+k] = sum_i S[col][i][f] * A[col][i][k] ----
    // task = (col, f): 512 tasks, 2 per thread; 20 accumulators each.
    #pragma unroll
    for (int pass = 0; pass < 2; pass++) {
        int id  = tid + pass*THR;
        int col = id >> 6, f = id & 63;
        float acc[20];
        #pragma unroll
        for (int k = 0; k < 20; k++) acc[k] = 0.f;
        const float* Sc = S  + col*FSTR + f;
        const float* Ac = AW + col*400;
        #pragma unroll
        for (int i = 0; i < 20; i++) {
            float sv = Sc[i*64];
            #pragma unroll
            for (int k = 0; k < 20; k++) acc[k] += sv * Ac[i*20 + k];
        }
        float* Fd = F + col*FSTR + f*20;
        #pragma unroll
        for (int k = 0; k < 20; k++) Fd[k] = acc[k];
    }
    __syncthreads();

    // ---- stage W4a (first 64 cols of W4) into AW with padded stride 68 ----
    for (int j = tid; j < 64*16; j += THR) {
        int o = j >> 4, q = j & 15;
        float4 v = ((const float4*)W4)[o*32 + q];
        float* d = &AW[o*68 + q*4];
        d[0]=v.x; d[1]=v.y; d[2]=v.z; d[3]=v.w;
    }
    __syncthreads();

    const int o0  = tid >> 3;        // 0..31
    const int o1  = o0 + 32;         // 32..63
    const int col = tid & 7;
    const int g   = g0 + col;

    // ---- out2: W2 @ feats  (8 independent accum chains) ----
    float a0x=0.f,a0y=0.f,a0z=0.f,a0w=0.f;
    float a1x=0.f,a1y=0.f,a1z=0.f,a1w=0.f;
    {
        const float4* w0 = (const float4*)(W2 + (size_t)o0*1280);
        const float4* w1 = (const float4*)(W2 + (size_t)o1*1280);
        const float4* fv = (const float4*)(F + col*FSTR);
        #pragma unroll 8
        for (int q = 0; q < 320; q++) {
            float4 fq = fv[q];
            float4 u  = w0[q], v = w1[q];
            a0x += fq.x*u.x; a0y += fq.y*u.y; a0z += fq.z*u.z; a0w += fq.w*u.w;
            a1x += fq.x*v.x; a1y += fq.y*v.y; a1z += fq.z*v.z; a1w += fq.w*v.w;
        }
    }
    float v20 = a0x + a0y + a0z + a0w + b2[o0];
    float v21 = a1x + a1y + a1z + a1w + b2[o1];

    // ---- out4: max_k (W4a @ S_k), k-chunked by 10 so W4a rows amortize ----
    float m0 = -FLT_MAX, m1 = -FLT_MAX;
    {
        const float4* wa = (const float4*)(AW + o0*68);
        const float4* wb = (const float4*)(AW + o1*68);
        #pragma unroll
        for (int kt = 0; kt < 2; kt++) {
            float s0[10], s1[10];
            #pragma unroll
            for (int k = 0; k < 10; k++) { s0[k]=0.f; s1[k]=0.f; }
            #pragma unroll
            for (int q = 0; q < 16; q++) {
                float4 u = wa[q], v = wb[q];
                #pragma unroll
                for (int k = 0; k < 10; k++) {
                    float4 sv = ((const float4*)(S + col*FSTR + (kt*10 + k)*64))[q];
                    s0[k] += sv.x*u.x + sv.y*u.y + sv.z*u.z + sv.w*u.w;
                    s1[k] += sv.x*v.x + sv.y*v.y + sv.z*v.z + sv.w*v.w;
                }
            }
            #pragma unroll
            for (int k = 0; k < 10; k++) { m0 = fmaxf(m0, s0[k]); m1 = fmaxf(m1, s1[k]); }
        }
    }

    // ---- dx = (W4b - W4a) @ x[:,n]  (k-invariant term) ----
    float d0a=0.f,d0b=0.f, d1a=0.f,d1b=0.f;
    {
        const float4* w4g = (const float4*)W4;
        const float4* xr4 = (const float4*)(XR + col*64);
        #pragma unroll
        for (int q = 0; q < 16; q++) {
            float4 xv = xr4[q];
            float4 A0 = w4g[o0*32 + q], B0 = w4g[o0*32 + 16 + q];
            float4 A1 = w4g[o1*32 + q], B1 = w4g[o1*32 + 16 + q];
            d0a += xv.x*(B0.x-A0.x) + xv.y*(B0.y-A0.y);
            d0b += xv.z*(B0.z-A0.z) + xv.w*(B0.w-A0.w);
            d1a += xv.x*(B1.x-A1.x) + xv.y*(B1.y-A1.y);
            d1b += xv.z*(B1.z-A1.z) + xv.w*(B1.w-A1.w);
        }
    }
    float v40 = m0 + d0a + d0b;
    float v41 = m1 + d1a + d1b;

    // ---- write pre-BN outputs ----
    {
        int b = g >> 11, n = g & 2047;
        size_t base = ((size_t)b*OUT_)*N_ + n;
        out[base + (size_t)o0*N_]        = v20;
        out[base + (size_t)o1*N_]        = v21;
        out[base + (size_t)(64+o0)*N_]   = v40;
        out[base + (size_t)(64+o1)*N_]   = v41;
    }

    // ---- deterministic per-block stats: butterfly over the 3 col bits ----
    float s20=v20, q20=v20*v20, s21=v21, q21=v21*v21;
    float s40=v40, q40=v40*v40, s41=v41, q41=v41*v41;
    #pragma unroll
    for (int off = 1; off < 8; off <<= 1) {
        s20 += __shfl_xor_sync(0xffffffffu, s20, off);
        q20 += __shfl_xor_sync(0xffffffffu, q20, off);
        s21 += __shfl_xor_sync(0xffffffffu, s21, off);
        q21 += __shfl_xor_sync(0xffffffffu, q21, off);
        s40 += __shfl_xor_sync(0xffffffffu, s40, off);
        q40 += __shfl_xor_sync(0xffffffffu, q40, off);
        s41 += __shfl_xor_sync(0xffffffffu, s41, off);
        q41 += __shfl_xor_sync(0xffffffffu, q41, off);
    }
    if (col == 0) {
        float* P = g_part + (size_t)blockIdx.x*(OUT_*2);
        P[o0*2]        = s20; P[o0*2 + 1]        = q20;
        P[o1*2]        = s21; P[o1*2 + 1]        = q21;
        P[(64+o0)*2]   = s40; P[(64+o0)*2 + 1]   = q40;
        P[(64+o1)*2]   = s41; P[(64+o1)*2 + 1]   = q41;
    }
}

// ============================================================
// Kernel 2: fixed-order reduction of partials -> scale/shift per channel
// ============================================================
__global__ void reduce_k(const float* __restrict__ gamma, const float* __restrict__ beta) {
    int ch = blockIdx.x;
    __shared__ float ss[256], sq[256];
    float s = 0.f, q = 0.f;
    for (int blk = threadIdx.x; blk < NBLK; blk += 256) {
        const float* P = g_part + (size_t)blk*(OUT_*2) + ch*2;
        s += P[0]; q += P[1];
    }
    ss[threadIdx.x] = s; sq[threadIdx.x] = q;
    __syncthreads();
    for (int off = 128; off > 0; off >>= 1) {
        if (threadIdx.x < off) {
            ss[threadIdx.x] += ss[threadIdx.x + off];
            sq[threadIdx.x] += sq[threadIdx.x + off];
        }
        __syncthreads();
    }
    if (threadIdx.x == 0) {
        float mean = ss[0] / (float)G_;
        float var  = sq[0] / (float)G_ - mean*mean;
        float sc   = gamma[ch] * rsqrtf(var + EPS_);
        g_scale[ch] = sc;
        g_shift[ch] = beta[ch] - mean*sc;
    }
}

// ============================================================
// Kernel 3: apply batchnorm in place (float4)
// ============================================================
__global__ void bn_k(float* __restrict__ out) {
    int i  = blockIdx.x*blockDim.x + threadIdx.x;     // over 1,048,576 float4
    int ch = (i >> 9) & 127;                          // 512 float4 per (b,ch) row
    float sc = g_scale[ch], sh = g_shift[ch];
    float4 v = ((float4*)out)[i];
    v.x = v.x*sc + sh; v.y = v.y*sc + sh;
    v.z = v.z*sc + sh; v.w = v.w*sc + sh;
    ((float4*)out)[i] = v;
}

// ============================================================
extern "C" void kernel_launch(void* const* d_in, const int* in_sizes, int n_in,
                              void* d_out, int out_size) {
    const float* x     = (const float*)d_in[0];
    const int*   sidx  = (const int*)  d_in[1];
    const float* adjw  = (const float*)d_in[2];
    const float* W2    = (const float*)d_in[3];
    const float* b2    = (const float*)d_in[4];
    const float* W4    = (const float*)d_in[5];
    const float* gamma = (const float*)d_in[6];
    const float* beta  = (const float*)d_in[7];
    float* out = (float*)d_out;

    dim3 tb(32, 8);
    dim3 tg(N_/32, C_/32, B_);
    transpose_k<<<tg, tb>>>(x);

    const int smem = (TN*FSTR*2 + 64*68 + TN*64) * (int)sizeof(float); // 101,632 B
    cudaFuncSetAttribute(main_k, cudaFuncAttributeMaxDynamicSharedMemorySize, smem);
    main_k<<<NBLK, THR, smem>>>(sidx, adjw, W2, b2, W4, out);

    reduce_k<<<OUT_, 256>>>(gamma, beta);
    bn_k<<<(G_*OUT_/4)/256, 256>>>(out);
}